// round 4
// baseline (speedup 1.0000x reference)
#include <cuda_runtime.h>

// LieTransport bilinear backward warp — cp.async smem-staged version.
// h_prev: [B=4, C=64, H=128, W=128, R=16] fp32 (64B per (c,y,x) pixel-vector)
// One 256-thread block per x-pixel PAIR (2x, 2x+1).
//
// Phase 1: stage, per pixel, per channel, the TOP (y0) and BOTTOM (y1) 128B
//          rows covering both x-taps, via cp.async.cg (L1-bypass, fire-and-
//          forget -> massive MLP without register pressure).
// Phase 2: blend from smem (conflict-free padded layout), store full 128B
//          lines per warp with .cs streaming hint.

#define Hd 128
#define Wd 128
#define Cd 64

#define ROWF 36                 // floats per staged 128B row (32 + 4 pad)
#define CHF  (2 * ROWF)         // 72 floats per channel (top+bottom rows)
#define PXF  (Cd * CHF + 4)     // 4612 floats per pixel section (+4 bank skew)
#define SMEMF (2 * PXF)         // 9224 floats = 36,896 B

__global__ __launch_bounds__(256) void lie_transport_kernel(
    const float* __restrict__ h,
    const float* __restrict__ flow,
    const float* __restrict__ dt,
    float*       __restrict__ out)
{
    __shared__ float s[SMEMF];

    const int tid = threadIdx.x;
    const int pp  = blockIdx.x;
    const int xp  = pp & (Wd / 2 - 1);       // x-pair index 0..63
    const int y   = (pp >> 6) & (Hd - 1);
    const int b   = pp >> 13;

    // ---- coordinates for BOTH pixels of the pair (uniform; redundant) ----
    const float d = dt[b];
    int   xs_[2], y0_[2], y1_[2], o0_[2], o1_[2];
    float wx_[2], wy_[2];
#pragma unroll
    for (int px = 0; px < 2; ++px) {
        const int x  = 2 * xp + px;
        const int fb = ((b * 2) * Hd + y) * Wd + x;
        const float fx = flow[fb];
        const float fy = flow[fb + Hd * Wd];

        const float gx = fmaf((float)x, 2.0f / (Wd - 1), -1.0f) - fx * d;
        const float gy = fmaf((float)y, 2.0f / (Hd - 1), -1.0f) - fy * d;

        const float ix = fminf(fmaxf(((gx + 1.0f) * (float)Wd - 1.0f) * 0.5f, 0.0f), (float)(Wd - 1));
        const float iy = fminf(fmaxf(((gy + 1.0f) * (float)Hd - 1.0f) * 0.5f, 0.0f), (float)(Hd - 1));

        const float x0f = floorf(ix);
        const float y0f = floorf(iy);
        wx_[px] = ix - x0f;
        wy_[px] = iy - y0f;

        const int x0 = (int)x0f;
        const int y0 = (int)y0f;
        const int x1 = min(x0 + 1, Wd - 1);
        y0_[px] = y0;
        y1_[px] = min(y0 + 1, Hd - 1);

        const int xs = min(x0, Wd - 2);   // 128B row start, never out of plane
        xs_[px] = xs;
        o0_[px] = x0 - xs;                // 0 or 1
        o1_[px] = x1 - xs;                // 0 or 1
    }

    unsigned s_u32;
    asm("{ .reg .u64 t; cvta.to.shared.u64 t, %1; cvt.u32.u64 %0, t; }"
        : "=r"(s_u32) : "l"(s));

    // ---- Phase 1: 2048 cp.async x 16B = 32KB of taps ----
    // op i -> chunk(8) x row(2) x ch(64) x px(2)
#pragma unroll
    for (int j = 0; j < 8; ++j) {
        const int i     = tid + 256 * j;
        const int chunk = i & 7;
        const int row   = (i >> 3) & 1;
        const int ch    = (i >> 4) & 63;
        const int px    = i >> 10;

        const int yrow = row ? y1_[px] : y0_[px];
        const int gidx = ((b * Cd + ch) * (Hd * Wd) + yrow * Wd + xs_[px]) * 16
                         + chunk * 4;                       // float index
        const unsigned daddr = s_u32 +
            (unsigned)(px * PXF + ch * CHF + row * ROWF + chunk * 4) * 4u;

        asm volatile("cp.async.cg.shared.global [%0], [%1], 16;\n"
                     :: "r"(daddr), "l"(h + gidx));
    }
    asm volatile("cp.async.commit_group;\n" ::: "memory");
    asm volatile("cp.async.wait_group 0;\n" ::: "memory");
    __syncthreads();

    // ---- Phase 2: blend + store ----
    const int q  = tid & 3;            // float4 quarter of R=16
    const int px = (tid >> 2) & 1;     // pixel of pair
    const int cg = tid >> 3;           // 0..31 -> channels cg, cg+32

    const float wx = wx_[px];
    const float wy = wy_[px];
    const int   o0 = o0_[px];
    const int   o1 = o1_[px];
    const int   sp = px * PXF;
    const int   x  = 2 * xp + px;

#pragma unroll
    for (int k = 0; k < 2; ++k) {
        const int ch = cg + 32 * k;
        const float4* rt = (const float4*)(s + sp + ch * CHF);         // top row
        const float4* rb = (const float4*)(s + sp + ch * CHF + ROWF);  // bottom

        const float4 v00 = rt[o0 * 4 + q];
        const float4 v01 = rt[o1 * 4 + q];
        const float4 v10 = rb[o0 * 4 + q];
        const float4 v11 = rb[o1 * 4 + q];

        float4 top, bot, r;
        top.x = fmaf(wx, v01.x - v00.x, v00.x);
        top.y = fmaf(wx, v01.y - v00.y, v00.y);
        top.z = fmaf(wx, v01.z - v00.z, v00.z);
        top.w = fmaf(wx, v01.w - v00.w, v00.w);
        bot.x = fmaf(wx, v11.x - v10.x, v10.x);
        bot.y = fmaf(wx, v11.y - v10.y, v10.y);
        bot.z = fmaf(wx, v11.z - v10.z, v10.z);
        bot.w = fmaf(wx, v11.w - v10.w, v10.w);
        r.x = fmaf(wy, bot.x - top.x, top.x);
        r.y = fmaf(wy, bot.y - top.y, top.y);
        r.z = fmaf(wy, bot.z - top.z, top.z);
        r.w = fmaf(wy, bot.w - top.w, top.w);

        // warp covers 4 channels x full aligned 128B lines (pixel pair)
        const int obase = (b * Cd + ch) * (Hd * Wd * 4) + (y * Wd + x) * 4 + q;
        __stcs((float4*)out + obase, r);
    }
}

extern "C" void kernel_launch(void* const* d_in, const int* in_sizes, int n_in,
                              void* d_out, int out_size)
{
    const float* h_prev = (const float*)d_in[0];
    const float* flow   = (const float*)d_in[1];
    const float* dt     = (const float*)d_in[2];
    float* out          = (float*)d_out;

    const int B = 4;
    dim3 grid(B * Hd * (Wd / 2));   // 32768 blocks, one per pixel pair
    dim3 block(256);

    lie_transport_kernel<<<grid, block>>>(h_prev, flow, dt, out);
}

// round 5
// speedup vs baseline: 1.4966x; 1.4966x over previous
#include <cuda_runtime.h>

// LieTransport bilinear backward warp — tap-tile-binned gather for L1 dedup.
// h_prev: [B=4, C=64, H=128, W=128, R=16] fp32 (64B per (b,c,y,x))
// flow:   [B, 2, H, W] fp32 ; dt: [B] fp32
//
// Problem: each input 64B sector is read ~4x by scattered output pixels ->
// 1 GB of L2->L1 traffic (LTS-bound ~110us). Fix: bin output pixels by the
// 8x8 input tile containing their top-left tap; one block processes one
// (tile, 4-channel group) -> tap working set 9x9x4x64B = 21KB, L1-resident,
// so the 4x reuse is served by L1 instead of L2.

#define Hd 128
#define Wd 128
#define Cd 64
#define Td 8
#define NTX (Wd / Td)              // 16 tiles per row
#define TPB (NTX * NTX)            // 256 tiles per batch
#define NT  (4 * TPB)              // 1024 tiles total
#define NPIX (4 * Hd * Wd)         // 65536 pixels

__device__ unsigned g_cnt[NT];
__device__ unsigned g_off[NT];
__device__ unsigned g_cur[NT];
__device__ uint2    g_rec[NPIX];

// ---- shared coordinate math (must exactly mirror the reference) ----
__device__ __forceinline__ void sample_coords(
    const float* __restrict__ flow, const float* __restrict__ dt,
    int b, int x, int y,
    int& x0, int& y0, float& wx, float& wy)
{
    const float d  = dt[b];
    const int   fb = ((b * 2) * Hd + y) * Wd + x;
    const float fx = flow[fb];
    const float fy = flow[fb + Hd * Wd];

    const float gx = fmaf((float)x, 2.0f / (Wd - 1), -1.0f) - fx * d;
    const float gy = fmaf((float)y, 2.0f / (Hd - 1), -1.0f) - fy * d;

    const float ix = fminf(fmaxf(((gx + 1.0f) * (float)Wd - 1.0f) * 0.5f, 0.0f), (float)(Wd - 1));
    const float iy = fminf(fmaxf(((gy + 1.0f) * (float)Hd - 1.0f) * 0.5f, 0.0f), (float)(Hd - 1));

    const float x0f = floorf(ix);
    const float y0f = floorf(iy);
    wx = ix - x0f;
    wy = iy - y0f;
    x0 = (int)x0f;
    y0 = (int)y0f;
}

// ---- K0: zero counters ----
__global__ void k_zero()
{
    g_cnt[threadIdx.x] = 0u;
}

// ---- K1: count pixels per (batch, tap tile) ----
__global__ __launch_bounds__(256) void k_count(
    const float* __restrict__ flow, const float* __restrict__ dt)
{
    const int pid = blockIdx.x * 256 + threadIdx.x;
    const int b = pid >> 14;
    const int y = (pid >> 7) & (Hd - 1);
    const int x = pid & (Wd - 1);

    int x0, y0; float wx, wy;
    sample_coords(flow, dt, b, x, y, x0, y0, wx, wy);

    const int tile = b * TPB + (y0 >> 3) * NTX + (x0 >> 3);
    atomicAdd(&g_cnt[tile], 1u);
}

// ---- K2: exclusive prefix sum over 1024 counters (single block) ----
__global__ void k_scan()
{
    __shared__ unsigned s[NT];
    const unsigned t = threadIdx.x;
    const unsigned v = g_cnt[t];
    s[t] = v;
    __syncthreads();
#pragma unroll
    for (int dstep = 1; dstep < NT; dstep <<= 1) {
        unsigned val = s[t];
        if ((int)t >= dstep) val += s[t - dstep];
        __syncthreads();
        s[t] = val;
        __syncthreads();
    }
    const unsigned excl = s[t] - v;
    g_off[t] = excl;
    g_cur[t] = excl;
}

// ---- K3: scatter packed pixel records into tile-segmented list ----
__global__ __launch_bounds__(256) void k_scatter(
    const float* __restrict__ flow, const float* __restrict__ dt)
{
    const int pid = blockIdx.x * 256 + threadIdx.x;
    const int b = pid >> 14;
    const int y = (pid >> 7) & (Hd - 1);
    const int x = pid & (Wd - 1);

    int x0, y0; float wx, wy;
    sample_coords(flow, dt, b, x, y, x0, y0, wx, wy);

    const int tile = b * TPB + (y0 >> 3) * NTX + (x0 >> 3);
    const unsigned idx = atomicAdd(&g_cur[tile], 1u);

    const unsigned wxq = min((unsigned)(wx * 65536.0f + 0.5f), 65535u);
    const unsigned wyq = min((unsigned)(wy * 65536.0f + 0.5f), 65535u);

    uint2 rec;
    rec.x = (unsigned)x | ((unsigned)y << 7) | ((unsigned)x0 << 14) | ((unsigned)y0 << 21);
    rec.y = wxq | (wyq << 16);
    g_rec[idx] = rec;
}

// ---- K4: main gather. Block = (tile, 4-channel group). ----
__global__ __launch_bounds__(256) void k_gather(
    const float4* __restrict__ h4,
    float4*       __restrict__ out4)
{
    const int tile = blockIdx.x;            // 0..1023
    const int cg   = blockIdx.y;            // 0..15 (4 channels each)
    const int b    = tile >> 8;

    const unsigned n  = g_cnt[tile];
    const unsigned s0 = g_off[tile];

    const int tid = threadIdx.x;
    const int q   = tid & 3;                // float4 quarter of R=16
    const int ch  = cg * 4 + ((tid >> 2) & 3);
    const int p0  = tid >> 4;               // 16 pixels per iteration

    // float4 plane base for this (b, ch): plane = H*W*4 float4s
    const int cbase = (b * Cd + ch) * (Hd * Wd * 4);

    for (unsigned i = p0; i < n; i += 16) {
        const uint2 rec = g_rec[s0 + i];
        const int x  = rec.x & 127;
        const int y  = (rec.x >> 7) & 127;
        const int x0 = (rec.x >> 14) & 127;
        const int y0 = (rec.x >> 21) & 127;
        const int x1 = min(x0 + 1, Wd - 1);
        const int y1 = min(y0 + 1, Hd - 1);
        const float wx = (float)(rec.y & 0xffffu) * (1.0f / 65536.0f);
        const float wy = (float)(rec.y >> 16)     * (1.0f / 65536.0f);

        const int i00 = cbase + (y0 * Wd + x0) * 4 + q;
        const int i01 = cbase + (y0 * Wd + x1) * 4 + q;
        const int i10 = cbase + (y1 * Wd + x0) * 4 + q;
        const int i11 = cbase + (y1 * Wd + x1) * 4 + q;

        const float4 v00 = __ldg(h4 + i00);
        const float4 v01 = __ldg(h4 + i01);
        const float4 v10 = __ldg(h4 + i10);
        const float4 v11 = __ldg(h4 + i11);

        float4 top, bot, r;
        top.x = fmaf(wx, v01.x - v00.x, v00.x);
        top.y = fmaf(wx, v01.y - v00.y, v00.y);
        top.z = fmaf(wx, v01.z - v00.z, v00.z);
        top.w = fmaf(wx, v01.w - v00.w, v00.w);
        bot.x = fmaf(wx, v11.x - v10.x, v10.x);
        bot.y = fmaf(wx, v11.y - v10.y, v10.y);
        bot.z = fmaf(wx, v11.z - v10.z, v10.z);
        bot.w = fmaf(wx, v11.w - v10.w, v10.w);
        r.x = fmaf(wy, bot.x - top.x, top.x);
        r.y = fmaf(wy, bot.y - top.y, top.y);
        r.z = fmaf(wy, bot.z - top.z, top.z);
        r.w = fmaf(wy, bot.w - top.w, top.w);

        __stcs(out4 + cbase + (y * Wd + x) * 4 + q, r);
    }
}

extern "C" void kernel_launch(void* const* d_in, const int* in_sizes, int n_in,
                              void* d_out, int out_size)
{
    const float* h_prev = (const float*)d_in[0];
    const float* flow   = (const float*)d_in[1];
    const float* dt     = (const float*)d_in[2];
    float* out          = (float*)d_out;

    k_zero<<<1, NT>>>();
    k_count<<<NPIX / 256, 256>>>(flow, dt);
    k_scan<<<1, NT>>>();
    k_scatter<<<NPIX / 256, 256>>>(flow, dt);

    dim3 grid(NT, Cd / 4);   // 1024 tiles x 16 channel groups
    k_gather<<<grid, 256>>>((const float4*)h_prev, (float4*)out);
}

// round 6
// speedup vs baseline: 1.8507x; 1.2366x over previous
#include <cuda_runtime.h>

// LieTransport bilinear backward warp — paired-span loads.
// h_prev: [B=4, C=64, H=128, W=128, R=16] fp32 (64B per (b,c,y,x) vector)
//
// Key fact: taps (y0,x0) and (y0,x0+1) are CONTIGUOUS 128B in memory.
// Load them as one 8-lane x 16B span per (row, pixel, channel) -> half the
// load instructions and ~25% fewer L1 wavefronts vs 4x64B scattered rows.
// y-blend per lane, then one float4 shfl_xor(4) exchanges the two x-halves
// for the x-blend. Stores: full 128B lines (pixel pair contiguous), .cs.
//
// Block = one x-pixel PAIR (2x,2x+1), 256 threads, grid 32768.
// lane = it*8 + e ; e = h*4 + q (h = span half, q = float4 quarter)
// it = k*2 + px   (px = pixel of pair, k = channel sub-slot)
// warp w, round j -> channel ch = j*16 + k*8 + w  (4 rounds cover 64 ch)

#define Hd 128
#define Wd 128
#define Cd 64
#define HWd (Hd * Wd)

__global__ __launch_bounds__(256) void lie_transport_kernel(
    const float4* __restrict__ h4,
    const float*  __restrict__ flow,
    const float*  __restrict__ dt,
    float4*       __restrict__ out4)
{
    const int tid  = threadIdx.x;
    const int lane = tid & 31;
    const int w    = tid >> 5;        // warp 0..7
    const int e    = lane & 7;        // position in 128B span
    const int h    = e >> 2;          // span half (x-tap 0 or 1)
    const int q    = e & 3;           // float4 quarter of R=16
    const int it   = lane >> 3;       // item 0..3
    const int px   = it & 1;          // pixel of pair
    const int k    = it >> 1;         // channel sub-slot 0..1

    const int pp = blockIdx.x;
    const int xp = pp & (Wd / 2 - 1);
    const int y  = (pp >> 6) & (Hd - 1);
    const int b  = pp >> 13;
    const int x  = 2 * xp + px;

    // ---- sampling coordinates for this thread's pixel ----
    const float d  = dt[b];
    const int   fb = ((b * 2) * Hd + y) * Wd + x;
    const float fx = flow[fb];
    const float fy = flow[fb + HWd];

    const float gx = fmaf((float)x, 2.0f / (Wd - 1), -1.0f) - fx * d;
    const float gy = fmaf((float)y, 2.0f / (Hd - 1), -1.0f) - fy * d;

    const float ix = fminf(fmaxf(((gx + 1.0f) * (float)Wd - 1.0f) * 0.5f, 0.0f), (float)(Wd - 1));
    const float iy = fminf(fmaxf(((gy + 1.0f) * (float)Hd - 1.0f) * 0.5f, 0.0f), (float)(Hd - 1));

    const float x0f = floorf(ix);
    const float y0f = floorf(iy);
    const float wx  = ix - x0f;
    const float wy  = iy - y0f;

    const int x0 = (int)x0f;
    const int y0 = (int)y0f;
    const int y1 = min(y0 + 1, Hd - 1);
    const int xs = min(x0, Wd - 2);          // span start (always in-bounds)

    // x-blend weights per span half. Normal: half0=x0 (1-wx), half1=x1 (wx).
    // Clamp case x0 = W-1: both taps are span half 1 -> weights (0, 1).
    const bool edge = (x0 == Wd - 1);
    const float c0 = edge ? 0.0f : (1.0f - wx);
    const float c1 = edge ? 1.0f : wx;
    const float cs = h ? c1 : c0;            // my half's weight
    const float co = h ? c0 : c1;            // other half's weight

    // ---- issue all 8 span loads up front (MLP = 8) ----
    const int plane0 = (b * Cd + (k * 8 + w)) * HWd;   // channel for j=0
    const int tbase  = (plane0 + y0 * Wd + xs) * 4 + e;
    const int bbase  = (plane0 + y1 * Wd + xs) * 4 + e;
    const int obase  = (plane0 + y  * Wd + x ) * 4 + q;
    const int jstep  = 16 * HWd * 4;                    // channel += 16 per round

    float4 t[4], bt[4];
#pragma unroll
    for (int j = 0; j < 4; ++j) {
        t[j]  = __ldg(h4 + tbase + j * jstep);
        bt[j] = __ldg(h4 + bbase + j * jstep);
    }

    // ---- per round: y-blend, shfl-exchange halves, x-blend, store ----
#pragma unroll
    for (int j = 0; j < 4; ++j) {
        float4 m;   // this half-column interpolated in y
        m.x = fmaf(wy, bt[j].x - t[j].x, t[j].x);
        m.y = fmaf(wy, bt[j].y - t[j].y, t[j].y);
        m.z = fmaf(wy, bt[j].z - t[j].z, t[j].z);
        m.w = fmaf(wy, bt[j].w - t[j].w, t[j].w);

        float4 mo;  // other half's column
        mo.x = __shfl_xor_sync(0xffffffffu, m.x, 4);
        mo.y = __shfl_xor_sync(0xffffffffu, m.y, 4);
        mo.z = __shfl_xor_sync(0xffffffffu, m.z, 4);
        mo.w = __shfl_xor_sync(0xffffffffu, m.w, 4);

        float4 r;
        r.x = fmaf(co, mo.x, cs * m.x);
        r.y = fmaf(co, mo.y, cs * m.y);
        r.z = fmaf(co, mo.z, cs * m.z);
        r.w = fmaf(co, mo.w, cs * m.w);

        // active lanes: it*8 + 0..3 -> per instr 2 full 128B output lines
        if (h == 0)
            __stcs(out4 + obase + j * jstep, r);
    }
}

extern "C" void kernel_launch(void* const* d_in, const int* in_sizes, int n_in,
                              void* d_out, int out_size)
{
    const float* h_prev = (const float*)d_in[0];
    const float* flow   = (const float*)d_in[1];
    const float* dt     = (const float*)d_in[2];
    float* out          = (float*)d_out;

    const int B = 4;
    dim3 grid(B * Hd * (Wd / 2));   // 32768 blocks, one per pixel pair
    dim3 block(256);

    lie_transport_kernel<<<grid, block>>>(
        (const float4*)h_prev, flow, dt, (float4*)out);
}